// round 11
// baseline (speedup 1.0000x reference)
#include <cuda_runtime.h>
#include <cuda_fp16.h>
#include <cstdint>

// Problem constants
#define BATCH  2
#define SEQ    2048
#define DIN    64
#define NHEAD  16
#define DHEAD  64
#define HB     32
#define HD     1024
#define NROWS  4096
#define DO     1024

#define ATTN_ELEMS 134217728LL
#define OUT_ELEMS  4194304LL

// fold 1/sqrt(64) and log2(e): scores kept in log2 domain
#define SCL (0.125f * 1.4426950408889634f)

// -------------------- scratch --------------------
__device__ float g_Qh[HB * SEQ * DHEAD];
__device__ float g_Kh[HB * SEQ * DHEAD];
__device__ float g_Vh[HB * SEQ * DHEAD];
__device__ float g_m[HB * SEQ];
__device__ float g_l[HB * SEQ];
__device__ float g_oh[NROWS * HD];
__device__ float g_attn_fb[134217728];

// -------------------- helpers --------------------
__device__ __forceinline__ uint32_t su32(const void* p) {
    uint32_t a;
    asm("{ .reg .u64 t; cvta.to.shared.u64 t, %1; cvt.u32.u64 %0, t; }" : "=r"(a) : "l"(p));
    return a;
}
__device__ __forceinline__ float ex2f(float x) {
    float y;
    asm("ex2.approx.f32 %0, %1;" : "=f"(y) : "f"(x));
    return y;
}
// f32 -> f16 hi/lo split of a float4: hp = hi halves, lp = lo halves
__device__ __forceinline__ void h2split(float4 v, uint2& hp, uint2& lp) {
    __half2 h0 = __floats2half2_rn(v.x, v.y);
    __half2 h1 = __floats2half2_rn(v.z, v.w);
    float2 f0 = __half22float2(h0), f1 = __half22float2(h1);
    __half2 l0 = __floats2half2_rn(v.x - f0.x, v.y - f0.y);
    __half2 l1 = __floats2half2_rn(v.z - f1.x, v.w - f1.y);
    hp.x = *(uint32_t*)&h0; hp.y = *(uint32_t*)&h1;
    lp.x = *(uint32_t*)&l0; lp.y = *(uint32_t*)&l1;
}
__device__ __forceinline__ void mma_f16(float* c, const uint32_t* a, const uint32_t* b) {
    asm volatile("mma.sync.aligned.m16n8k16.row.col.f32.f16.f16.f32 "
                 "{%0,%1,%2,%3}, {%4,%5,%6,%7}, {%8,%9}, {%0,%1,%2,%3};"
                 : "+f"(c[0]), "+f"(c[1]), "+f"(c[2]), "+f"(c[3])
                 : "r"(a[0]), "r"(a[1]), "r"(a[2]), "r"(a[3]), "r"(b[0]), "r"(b[1]));
}
__device__ __forceinline__ void ldmA(uint32_t* r, uint32_t addr) {
    asm volatile("ldmatrix.sync.aligned.m8n8.x4.shared.b16 {%0,%1,%2,%3}, [%4];"
                 : "=r"(r[0]), "=r"(r[1]), "=r"(r[2]), "=r"(r[3]) : "r"(addr));
}
// trans x4: two B fragments (adjacent 8-col groups) in one op
__device__ __forceinline__ void ldmB4(uint32_t* r, uint32_t addr) {
    asm volatile("ldmatrix.sync.aligned.m8n8.x4.trans.shared.b16 {%0,%1,%2,%3}, [%4];"
                 : "=r"(r[0]), "=r"(r[1]), "=r"(r[2]), "=r"(r[3]) : "r"(addr));
}
// non-trans x4: two B fragments (adjacent 8-key groups) in one op
__device__ __forceinline__ void ldmBn4(uint32_t* r, uint32_t addr) {
    asm volatile("ldmatrix.sync.aligned.m8n8.x4.shared.b16 {%0,%1,%2,%3}, [%4];"
                 : "=r"(r[0]), "=r"(r[1]), "=r"(r[2]), "=r"(r[3]) : "r"(addr));
}

// ==================== kernel 1: fused QKV projections ====================
__global__ __launch_bounds__(256) void proj_fused_kernel(
    const float* __restrict__ q, const float* __restrict__ k, const float* __restrict__ v,
    const float* __restrict__ Wq, const float* __restrict__ bq,
    const float* __restrict__ Wk, const float* __restrict__ bk,
    const float* __restrict__ Wv, const float* __restrict__ bv,
    float* __restrict__ Qh, float* __restrict__ Kh, float* __restrict__ Vh) {
    __shared__ float Xs[64][65];
    __shared__ float Ws[64][65];
    int rt = blockIdx.x, head = blockIdx.y, z = blockIdx.z, tid = threadIdx.x;
    const float* X = (z == 0) ? q : (z == 1) ? k : v;
    const float* W = (z == 0) ? Wq : (z == 1) ? Wk : Wv;
    const float* bias = (z == 0) ? bq : (z == 1) ? bk : bv;
    float* Out = (z == 0) ? Qh : (z == 1) ? Kh : Vh;

#pragma unroll
    for (int t = 0; t < 4; t++) {
        int f = tid + t * 256;
        int r = f >> 4, c = (f & 15) << 2;
        float4 xv = *(const float4*)(X + (size_t)(rt * 64 + r) * DIN + c);
        Xs[r][c] = xv.x; Xs[r][c + 1] = xv.y; Xs[r][c + 2] = xv.z; Xs[r][c + 3] = xv.w;
        float4 wv = *(const float4*)(W + (size_t)r * HD + head * 64 + c);
        Ws[r][c] = wv.x; Ws[r][c + 1] = wv.y; Ws[r][c + 2] = wv.z; Ws[r][c + 3] = wv.w;
    }
    __syncthreads();
    int ty = tid >> 4, tx = tid & 15;
    int r0 = ty * 4, c0 = tx * 4;
    float acc[4][4] = {};
#pragma unroll
    for (int kk = 0; kk < 64; kk++) {
        float a[4], b[4];
#pragma unroll
        for (int i = 0; i < 4; i++) a[i] = Xs[r0 + i][kk];
#pragma unroll
        for (int j = 0; j < 4; j++) b[j] = Ws[kk][c0 + j];
#pragma unroll
        for (int i = 0; i < 4; i++)
#pragma unroll
            for (int j = 0; j < 4; j++) acc[i][j] = fmaf(a[i], b[j], acc[i][j]);
    }
    int bb = (rt * 64) / SEQ;
    int nbase = rt * 64 - bb * SEQ;
    float bv4[4];
#pragma unroll
    for (int j = 0; j < 4; j++) bv4[j] = bias[head * 64 + c0 + j];
#pragma unroll
    for (int i = 0; i < 4; i++) {
        float4 o;
        o.x = acc[i][0] + bv4[0]; o.y = acc[i][1] + bv4[1];
        o.z = acc[i][2] + bv4[2]; o.w = acc[i][3] + bv4[3];
        size_t row = (size_t)(head * BATCH + bb) * SEQ + nbase + r0 + i;
        *(float4*)(Out + row * DHEAD + c0) = o;
    }
}

// ==================== kernel 2: scores via f16-3x m16n8k16 ====================
// 512 threads, 16 warps; warp = (wr 0..3 rowgroup of 32, wq 0..3 colquad of 32)
#define SC_QH 0
#define SC_QL 18432
#define SC_KB0 36864
#define SC_KBSTRIDE 36864
#define SC_STATS 110592
#define SC_SMEM_BYTES 114688

__global__ __launch_bounds__(512, 1) void scores_mma_kernel(float* __restrict__ attn) {
    extern __shared__ char smc[];
    uint32_t sb = su32(smc);

    int tid = threadIdx.x, lane = tid & 31, w = tid >> 5;
    int g = lane >> 2, tg = lane & 3;
    int wr = w & 3, wq = w >> 2;
    int hb = blockIdx.x, qt = blockIdx.y;
    int r1 = wr * 32 + g;

    // ---- load Q (log2 domain, f16 hi/lo split), row-major [row][dim] stride 72 halves ----
    const float* Qp = g_Qh + ((size_t)hb * SEQ + qt * 128) * DHEAD;
#pragma unroll
    for (int t = 0; t < 4; t++) {
        int f = tid + t * 512;
        int r = f >> 4, c = (f & 15) << 2;
        float4 v = *(const float4*)(Qp + (size_t)r * DHEAD + c);
        v.x *= SCL; v.y *= SCL; v.z *= SCL; v.w *= SCL;
        uint2 hp, lp;
        h2split(v, hp, lp);
        *(uint2*)(smc + SC_QH + (r * 72 + c) * 2) = hp;
        *(uint2*)(smc + SC_QL + (r * 72 + c) * 2) = lp;
    }
    // ---- prologue: K tile 0 -> buf0 ----
    {
        const float* Kp = g_Kh + ((size_t)hb * SEQ) * DHEAD;
#pragma unroll
        for (int t = 0; t < 4; t++) {
            int f = tid + t * 512;
            int r = f >> 4, c = (f & 15) << 2;
            float4 v = *(const float4*)(Kp + (size_t)r * DHEAD + c);
            uint2 hp, lp;
            h2split(v, hp, lp);
            *(uint2*)(smc + SC_KB0 + (r * 72 + c) * 2) = hp;
            *(uint2*)(smc + SC_KB0 + 18432 + (r * 72 + c) * 2) = lp;
        }
    }
    __syncthreads();

    float mA[2] = {-1e30f, -1e30f}, lA[2] = {0.f, 0.f};
    float mB[2] = {-1e30f, -1e30f}, lB[2] = {0.f, 0.f};
    float* Tbase = attn + (size_t)hb * SEQ * SEQ + (size_t)(qt * 128) * SEQ;

    int arow = (lane & 15);
    int acl = ((lane >> 4) & 1) * 8;
    // x4 non-trans B addressing: lanes 0-7 m0(keys,d0-7), 8-15 m1(keys,d8-15),
    // 16-23 m2(keys+8,d0-7), 24-31 m3(keys+8,d8-15)
    int bkey4 = wq * 32 + (lane & 7) + ((lane >> 4) & 1) * 8;
    int bdim4 = ((lane >> 3) & 1) * 8;

    for (int kt = 0; kt < 16; kt++) {
        float4 pre[4];
        if (kt < 15) {
            const float* Kp = g_Kh + ((size_t)hb * SEQ + (kt + 1) * 128) * DHEAD;
#pragma unroll
            for (int t = 0; t < 4; t++) {
                int f = tid + t * 512;
                int r = f >> 4, c = (f & 15) << 2;
                pre[t] = *(const float4*)(Kp + (size_t)r * DHEAD + c);
            }
        }
        uint32_t kbH = sb + SC_KB0 + (kt & 1) * SC_KBSTRIDE;
        uint32_t kbL = kbH + 18432;

        float C[2][4][4];
#pragma unroll
        for (int mt = 0; mt < 2; mt++)
#pragma unroll
            for (int j = 0; j < 4; j++) { C[mt][j][0] = C[mt][j][1] = C[mt][j][2] = C[mt][j][3] = 0.f; }

#pragma unroll
        for (int ks = 0; ks < 4; ks++) {
            uint32_t aH[2][4], aL[2][4];
#pragma unroll
            for (int mt = 0; mt < 2; mt++) {
                uint32_t off = (uint32_t)(((wr * 32 + mt * 16 + arow) * 72 + ks * 16 + acl) * 2);
                ldmA(aH[mt], sb + SC_QH + off);
                ldmA(aL[mt], sb + SC_QL + off);
            }
#pragma unroll
            for (int jp = 0; jp < 2; jp++) {
                uint32_t boff = (uint32_t)(((bkey4 + jp * 16) * 72 + ks * 16 + bdim4) * 2);
                uint32_t b4H[4], b4L[4];
                ldmBn4(b4H, kbH + boff);
                ldmBn4(b4L, kbL + boff);
#pragma unroll
                for (int jj = 0; jj < 2; jj++)
#pragma unroll
                    for (int mt = 0; mt < 2; mt++) {
                        float* Cp = C[mt][jp * 2 + jj];
                        mma_f16(Cp, aH[mt], b4H + jj * 2);
                        mma_f16(Cp, aH[mt], b4L + jj * 2);
                        mma_f16(Cp, aL[mt], b4H + jj * 2);
                    }
            }
        }

        // online partial stats over this warp's 32 columns
#pragma unroll
        for (int mt = 0; mt < 2; mt++) {
            float mxa = C[mt][0][0], mxb = C[mt][0][2];
#pragma unroll
            for (int j = 0; j < 4; j++) {
                mxa = fmaxf(mxa, fmaxf(C[mt][j][0], C[mt][j][1]));
                mxb = fmaxf(mxb, fmaxf(C[mt][j][2], C[mt][j][3]));
            }
            mxa = fmaxf(mxa, __shfl_xor_sync(0xffffffffu, mxa, 1));
            mxa = fmaxf(mxa, __shfl_xor_sync(0xffffffffu, mxa, 2));
            mxb = fmaxf(mxb, __shfl_xor_sync(0xffffffffu, mxb, 1));
            mxb = fmaxf(mxb, __shfl_xor_sync(0xffffffffu, mxb, 2));
            float M1 = fmaxf(mA[mt], mxa), M2 = fmaxf(mB[mt], mxb);
            float sa = 0.f, sb2 = 0.f;
#pragma unroll
            for (int j = 0; j < 4; j++) {
                sa  += ex2f(C[mt][j][0] - M1) + ex2f(C[mt][j][1] - M1);
                sb2 += ex2f(C[mt][j][2] - M2) + ex2f(C[mt][j][3] - M2);
            }
            sa  += __shfl_xor_sync(0xffffffffu, sa, 1);
            sa  += __shfl_xor_sync(0xffffffffu, sa, 2);
            sb2 += __shfl_xor_sync(0xffffffffu, sb2, 1);
            sb2 += __shfl_xor_sync(0xffffffffu, sb2, 2);
            lA[mt] = lA[mt] * ex2f(mA[mt] - M1) + sa;  mA[mt] = M1;
            lB[mt] = lB[mt] * ex2f(mB[mt] - M2) + sb2; mB[mt] = M2;
        }

        // store raw log2-domain scores
#pragma unroll
        for (int mt = 0; mt < 2; mt++) {
            int rr = r1 + mt * 16;
            float* p1 = Tbase + (size_t)rr * SEQ + kt * 128 + wq * 32 + 2 * tg;
            float* p2 = p1 + (size_t)8 * SEQ;
#pragma unroll
            for (int j = 0; j < 4; j++) {
                *(float2*)(p1 + j * 8) = make_float2(C[mt][j][0], C[mt][j][1]);
                *(float2*)(p2 + j * 8) = make_float2(C[mt][j][2], C[mt][j][3]);
            }
        }

        if (kt < 15) {
            char* kb = smc + SC_KB0 + ((kt + 1) & 1) * SC_KBSTRIDE;
#pragma unroll
            for (int t = 0; t < 4; t++) {
                int f = tid + t * 512;
                int r = f >> 4, c = (f & 15) << 2;
                uint2 hp, lp;
                h2split(pre[t], hp, lp);
                *(uint2*)(kb + (r * 72 + c) * 2) = hp;
                *(uint2*)(kb + 18432 + (r * 72 + c) * 2) = lp;
            }
        }
        __syncthreads();
    }

    // combine 4 column-quad partials per row
    float* smm = (float*)(smc + SC_STATS);
    float* sml = smm + 512;
    if (tg == 0) {
#pragma unroll
        for (int mt = 0; mt < 2; mt++) {
            int rr = r1 + mt * 16;
            smm[wq * 128 + rr] = mA[mt];      sml[wq * 128 + rr] = lA[mt];
            smm[wq * 128 + rr + 8] = mB[mt];  sml[wq * 128 + rr + 8] = lB[mt];
        }
    }
    __syncthreads();
    if (tid < 128) {
        float M = smm[tid];
#pragma unroll
        for (int qd = 1; qd < 4; qd++) M = fmaxf(M, smm[qd * 128 + tid]);
        float L = 0.f;
#pragma unroll
        for (int qd = 0; qd < 4; qd++) L += sml[qd * 128 + tid] * ex2f(smm[qd * 128 + tid] - M);
        int base = hb * SEQ + qt * 128;
        g_m[base + tid] = M;
        g_l[base + tid] = L;
    }
}

// ==================== kernel 3: normalize + PV, 256 thr, m=32 warps, 2 CTA/SM ====================
// 8 warps: wr 0..3 (32 rows each), wc 0..1 (32 dims each)
#define PV_PBUF 55296
#define PV_STAT 110592
#define PV_SMEM_BYTES 111616

__global__ __launch_bounds__(256, 2) void pv_mma_kernel(float* __restrict__ attn) {
    extern __shared__ char smc[];
    uint32_t sb = su32(smc);
    float* msm  = (float*)(smc + PV_STAT);
    float* ilsm = (float*)(smc + PV_STAT + 512);

    int tid = threadIdx.x, lane = tid & 31, w = tid >> 5;
    int g = lane >> 2, tg = lane & 3;
    int wr = w & 3, wc = w >> 2;
    int hb = blockIdx.x, qt = blockIdx.y;

    if (tid < 128) {
        msm[tid] = g_m[hb * SEQ + qt * 128 + tid];
        ilsm[tid] = 1.0f / g_l[hb * SEQ + qt * 128 + tid];
    }
    __syncthreads();

    float* arow = attn + (size_t)hb * SEQ * SEQ + (size_t)(qt * 128) * SEQ;
    float C[2][4][4];
#pragma unroll
    for (int mt = 0; mt < 2; mt++)
#pragma unroll
        for (int j = 0; j < 4; j++) { C[mt][j][0] = C[mt][j][1] = C[mt][j][2] = C[mt][j][3] = 0.f; }

    float4 aR[8], vR[4];
    // prologue: load + process chunk 0 into buf 0
    {
        const float* Vp = g_Vh + ((size_t)hb * SEQ) * DHEAD;
#pragma unroll
        for (int t = 0; t < 8; t++) {
            int f = tid + t * 256;
            int r = f >> 4, c = (f & 15) << 2;
            aR[t] = *(const float4*)(arow + (size_t)r * SEQ + c);
        }
#pragma unroll
        for (int t = 0; t < 4; t++) {
            int f = tid + t * 256;
            int kk = f >> 4, dd = (f & 15) << 2;
            vR[t] = *(const float4*)(Vp + (size_t)kk * DHEAD + dd);
        }
        char* bufc = smc;
#pragma unroll
        for (int t = 0; t < 8; t++) {
            int f = tid + t * 256;
            int r = f >> 4, c = (f & 15) << 2;
            float4 v = aR[t];
            float mm = msm[r], il = ilsm[r];
            v.x = ex2f(v.x - mm) * il; v.y = ex2f(v.y - mm) * il;
            v.z = ex2f(v.z - mm) * il; v.w = ex2f(v.w - mm) * il;
            *(float4*)(arow + (size_t)r * SEQ + c) = v;
            uint2 hp, lp;
            h2split(v, hp, lp);
            *(uint2*)(bufc + (r * 72 + c) * 2) = hp;
            *(uint2*)(bufc + 18432 + (r * 72 + c) * 2) = lp;
        }
#pragma unroll
        for (int t = 0; t < 4; t++) {
            int f = tid + t * 256;
            int kk = f >> 4, dd = (f & 15) << 2;
            uint2 hp, lp;
            h2split(vR[t], hp, lp);
            *(uint2*)(bufc + 36864 + (kk * 72 + dd) * 2) = hp;
            *(uint2*)(bufc + 46080 + (kk * 72 + dd) * 2) = lp;
        }
    }
    __syncthreads();

    int arow16 = (lane & 15);
    int acl = ((lane >> 4) & 1) * 8;
    int brow4 = (lane & 15);
    int bcol4 = wc * 32 + ((lane >> 4) & 1) * 8;

    for (int kc = 0; kc < 32; kc++) {
        int b = kc & 1;
        if (kc < 31) {
            const float* Vp = g_Vh + ((size_t)hb * SEQ + (kc + 1) * 64) * DHEAD;
#pragma unroll
            for (int t = 0; t < 8; t++) {
                int f = tid + t * 256;
                int r = f >> 4, c = (f & 15) << 2;
                aR[t] = *(const float4*)(arow + (size_t)r * SEQ + (kc + 1) * 64 + c);
            }
#pragma unroll
            for (int t = 0; t < 4; t++) {
                int f = tid + t * 256;
                int kk = f >> 4, dd = (f & 15) << 2;
                vR[t] = *(const float4*)(Vp + (size_t)kk * DHEAD + dd);
            }
        }
        uint32_t bufb = sb + b * PV_PBUF;
#pragma unroll
        for (int s = 0; s < 4; s++) {
            uint32_t aH[2][4], aL[2][4];
#pragma unroll
            for (int mt = 0; mt < 2; mt++) {
                uint32_t off = (uint32_t)(((wr * 32 + mt * 16 + arow16) * 72 + s * 16 + acl) * 2);
                ldmA(aH[mt], bufb + off);
                ldmA(aL[mt], bufb + 18432 + off);
            }
#pragma unroll
            for (int jp = 0; jp < 2; jp++) {
                uint32_t boff = (uint32_t)(((s * 16 + brow4) * 72 + bcol4 + jp * 16) * 2);
                uint32_t b4H[4], b4L[4];
                ldmB4(b4H, bufb + 36864 + boff);
                ldmB4(b4L, bufb + 46080 + boff);
#pragma unroll
                for (int jj = 0; jj < 2; jj++)
#pragma unroll
                    for (int mt = 0; mt < 2; mt++) {
                        float* Cp = C[mt][jp * 2 + jj];
                        mma_f16(Cp, aH[mt], b4H + jj * 2);
                        mma_f16(Cp, aH[mt], b4L + jj * 2);
                        mma_f16(Cp, aL[mt], b4H + jj * 2);
                    }
            }
        }
        if (kc < 31) {
            char* bufc = smc + (b ^ 1) * PV_PBUF;
#pragma unroll
            for (int t = 0; t < 8; t++) {
                int f = tid + t * 256;
                int r = f >> 4, c = (f & 15) << 2;
                float4 v = aR[t];
                float mm = msm[r], il = ilsm[r];
                v.x = ex2f(v.x - mm) * il; v.y = ex2f(v.y - mm) * il;
                v.z = ex2f(v.z - mm) * il; v.w = ex2f(v.w - mm) * il;
                *(float4*)(arow + (size_t)r * SEQ + (kc + 1) * 64 + c) = v;
                uint2 hp, lp;
                h2split(v, hp, lp);
                *(uint2*)(bufc + (r * 72 + c) * 2) = hp;
                *(uint2*)(bufc + 18432 + (r * 72 + c) * 2) = lp;
            }
#pragma unroll
            for (int t = 0; t < 4; t++) {
                int f = tid + t * 256;
                int kk = f >> 4, dd = (f & 15) << 2;
                uint2 hp, lp;
                h2split(vR[t], hp, lp);
                *(uint2*)(bufc + 36864 + (kk * 72 + dd) * 2) = hp;
                *(uint2*)(bufc + 46080 + (kk * 72 + dd) * 2) = lp;
            }
        }
        __syncthreads();
    }

    int h = hb >> 1, bb = hb & 1;
#pragma unroll
    for (int mt = 0; mt < 2; mt++) {
        int r1 = wr * 32 + mt * 16 + g;
        float* o1 = g_oh + ((size_t)(bb * SEQ + qt * 128 + r1)) * HD + h * 64 + wc * 32 + 2 * tg;
        float* o2 = o1 + 8 * HD;
#pragma unroll
        for (int j = 0; j < 4; j++) {
            *(float2*)(o1 + j * 8) = make_float2(C[mt][j][0], C[mt][j][1]);
            *(float2*)(o2 + j * 8) = make_float2(C[mt][j][2], C[mt][j][3]);
        }
    }
}

// ==================== kernel 4: out projection, 256 thr, m=32 warps, kstep 32 ====================
// 8 warps: wr 0..3 (32 rows), wc 0..1 (64 cols). Buffer: AH 0, AL 10240, BH 20480, BL 29184
#define OP_PBUF 37888
#define OP_SMEM_BYTES 75776

__global__ __launch_bounds__(256, 2) void oproj_mma_kernel(
    const float* __restrict__ Wo, const float* __restrict__ bo, float* __restrict__ out) {
    extern __shared__ char smc[];
    uint32_t sb = su32(smc);

    int tid = threadIdx.x, lane = tid & 31, w = tid >> 5;
    int g = lane >> 2, tg = lane & 3;
    int wr = w & 3, wc = w >> 2;
    int rt = blockIdx.x, ct = blockIdx.y;

    float C[2][8][4];
#pragma unroll
    for (int mt = 0; mt < 2; mt++)
#pragma unroll
        for (int j = 0; j < 8; j++) { C[mt][j][0] = C[mt][j][1] = C[mt][j][2] = C[mt][j][3] = 0.f; }

    float4 aR[4], bR[4];
    // prologue: chunk 0 -> buf 0
    {
#pragma unroll
        for (int t = 0; t < 4; t++) {
            int f = tid + t * 256;
            int r = f >> 3, c = (f & 7) << 2;
            aR[t] = *(const float4*)(g_oh + (size_t)(rt * 128 + r) * HD + c);
        }
#pragma unroll
        for (int t = 0; t < 4; t++) {
            int f = tid + t * 256;
            int kk = f >> 5, nn = (f & 31) << 2;
            bR[t] = *(const float4*)(Wo + (size_t)kk * DO + ct * 128 + nn);
        }
        char* bufc = smc;
#pragma unroll
        for (int t = 0; t < 4; t++) {
            int f = tid + t * 256;
            int r = f >> 3, c = (f & 7) << 2;
            uint2 hp, lp;
            h2split(aR[t], hp, lp);
            *(uint2*)(bufc + (r * 40 + c) * 2) = hp;
            *(uint2*)(bufc + 10240 + (r * 40 + c) * 2) = lp;
        }
#pragma unroll
        for (int t = 0; t < 4; t++) {
            int f = tid + t * 256;
            int kk = f >> 5, nn = (f & 31) << 2;
            uint2 hp, lp;
            h2split(bR[t], hp, lp);
            *(uint2*)(bufc + 20480 + (kk * 136 + nn) * 2) = hp;
            *(uint2*)(bufc + 29184 + (kk * 136 + nn) * 2) = lp;
        }
    }
    __syncthreads();

    int arow16 = (lane & 15);
    int acl = ((lane >> 4) & 1) * 8;
    int brow4 = (lane & 15);
    int bcol4 = wc * 64 + ((lane >> 4) & 1) * 8;

    for (int kc = 0; kc < 32; kc++) {
        int b = kc & 1;
        if (kc < 31) {
#pragma unroll
            for (int t = 0; t < 4; t++) {
                int f = tid + t * 256;
                int r = f >> 3, c = (f & 7) << 2;
                aR[t] = *(const float4*)(g_oh + (size_t)(rt * 128 + r) * HD + (kc + 1) * 32 + c);
            }
#pragma unroll
            for (int t = 0; t < 4; t++) {
                int f = tid + t * 256;
                int kk = f >> 5, nn = (f & 31) << 2;
                bR[t] = *(const float4*)(Wo + (size_t)((kc + 1) * 32 + kk) * DO + ct * 128 + nn);
            }
        }
        uint32_t bufb = sb + b * OP_PBUF;
#pragma unroll
        for (int s = 0; s < 2; s++) {
            uint32_t aH[2][4], aL[2][4];
#pragma unroll
            for (int mt = 0; mt < 2; mt++) {
                uint32_t off = (uint32_t)(((wr * 32 + mt * 16 + arow16) * 40 + s * 16 + acl) * 2);
                ldmA(aH[mt], bufb + off);
                ldmA(aL[mt], bufb + 10240 + off);
            }
#pragma unroll
            for (int jp = 0; jp < 4; jp++) {
                uint32_t boff = (uint32_t)(((s * 16 + brow4) * 136 + bcol4 + jp * 16) * 2);
                uint32_t b4H[4], b4L[4];
                ldmB4(b4H, bufb + 20480 + boff);
                ldmB4(b4L, bufb + 29184 + boff);
#pragma unroll
                for (int jj = 0; jj < 2; jj++)
#pragma unroll
                    for (int mt = 0; mt < 2; mt++) {
                        float* Cp = C[mt][jp * 2 + jj];
                        mma_f16(Cp, aH[mt], b4H + jj * 2);
                        mma_f16(Cp, aH[mt], b4L + jj * 2);
                        mma_f16(Cp, aL[mt], b4H + jj * 2);
                    }
            }
        }
        if (kc < 31) {
            char* bufc = smc + (b ^ 1) * OP_PBUF;
#pragma unroll
            for (int t = 0; t < 4; t++) {
                int f = tid + t * 256;
                int r = f >> 3, c = (f & 7) << 2;
                uint2 hp, lp;
                h2split(aR[t], hp, lp);
                *(uint2*)(bufc + (r * 40 + c) * 2) = hp;
                *(uint2*)(bufc + 10240 + (r * 40 + c) * 2) = lp;
            }
#pragma unroll
            for (int t = 0; t < 4; t++) {
                int f = tid + t * 256;
                int kk = f >> 5, nn = (f & 31) << 2;
                uint2 hp, lp;
                h2split(bR[t], hp, lp);
                *(uint2*)(bufc + 20480 + (kk * 136 + nn) * 2) = hp;
                *(uint2*)(bufc + 29184 + (kk * 136 + nn) * 2) = lp;
            }
        }
        __syncthreads();
    }

#pragma unroll
    for (int mt = 0; mt < 2; mt++) {
        int r1 = wr * 32 + mt * 16 + g;
        const float* bp = bo + ct * 128 + wc * 64;
        float* o1 = out + (size_t)(rt * 128 + r1) * DO + ct * 128 + wc * 64 + 2 * tg;
        float* o2 = o1 + 8 * DO;
#pragma unroll
        for (int j = 0; j < 8; j++) {
            int cc = j * 8 + 2 * tg;
            *(float2*)(o1 + j * 8) = make_float2(C[mt][j][0] + bp[cc], C[mt][j][1] + bp[cc + 1]);
            *(float2*)(o2 + j * 8) = make_float2(C[mt][j][2] + bp[cc], C[mt][j][3] + bp[cc + 1]);
        }
    }
}

// ==================== launch ====================
extern "C" void kernel_launch(void* const* d_in, const int* in_sizes, int n_in,
                              void* d_out, int out_size) {
    const float* q  = (const float*)d_in[0];
    const float* k  = (const float*)d_in[1];
    const float* v  = (const float*)d_in[2];
    const float* Wq = (const float*)d_in[3];
    const float* bq = (const float*)d_in[4];
    const float* Wk = (const float*)d_in[5];
    const float* bk = (const float*)d_in[6];
    const float* Wv = (const float*)d_in[7];
    const float* bv = (const float*)d_in[8];
    const float* Wo = (const float*)d_in[9];
    const float* bo = (const float*)d_in[10];
    (void)in_sizes; (void)n_in;

    long long osz = (long long)out_size;
    float* attn = nullptr;
    float* out  = nullptr;
    if (osz >= ATTN_ELEMS + OUT_ELEMS) {
        attn = (float*)d_out;
        out  = (float*)d_out + ATTN_ELEMS;
    } else if (osz >= ATTN_ELEMS) {
        attn = (float*)d_out;
    } else {
        out = (float*)d_out;
    }
    if (!attn) cudaGetSymbolAddress((void**)&attn, g_attn_fb);

    float *Qh, *Kh, *Vh;
    cudaGetSymbolAddress((void**)&Qh, g_Qh);
    cudaGetSymbolAddress((void**)&Kh, g_Kh);
    cudaGetSymbolAddress((void**)&Vh, g_Vh);

    cudaFuncSetAttribute(scores_mma_kernel, cudaFuncAttributeMaxDynamicSharedMemorySize, SC_SMEM_BYTES);
    cudaFuncSetAttribute(pv_mma_kernel, cudaFuncAttributeMaxDynamicSharedMemorySize, PV_SMEM_BYTES);
    cudaFuncSetAttribute(oproj_mma_kernel, cudaFuncAttributeMaxDynamicSharedMemorySize, OP_SMEM_BYTES);

    proj_fused_kernel<<<dim3(64, 16, 3), 256>>>(q, k, v, Wq, bq, Wk, bk, Wv, bv, Qh, Kh, Vh);
    scores_mma_kernel<<<dim3(HB, 16), 512, SC_SMEM_BYTES>>>(attn);
    pv_mma_kernel<<<dim3(HB, 16), 256, PV_SMEM_BYTES>>>(attn);
    if (out) oproj_mma_kernel<<<dim3(32, 8), 256, OP_SMEM_BYTES>>>(Wo, bo, out);
}

// round 13
// speedup vs baseline: 1.5870x; 1.5870x over previous
#include <cuda_runtime.h>
#include <cuda_fp16.h>
#include <cstdint>

// Problem constants
#define BATCH  2
#define SEQ    2048
#define DIN    64
#define NHEAD  16
#define DHEAD  64
#define HB     32
#define HD     1024
#define NROWS  4096
#define DO     1024

#define ATTN_ELEMS 134217728LL
#define OUT_ELEMS  4194304LL

// fold 1/sqrt(64) and log2(e): scores kept in log2 domain
#define SCL (0.125f * 1.4426950408889634f)

// -------------------- scratch --------------------
__device__ float g_Qh[HB * SEQ * DHEAD];
__device__ float g_Kh[HB * SEQ * DHEAD];
__device__ float g_Vh[HB * SEQ * DHEAD];
__device__ float g_m[HB * SEQ];
__device__ float g_l[HB * SEQ];
__device__ float g_oh[NROWS * HD];
__device__ float g_attn_fb[134217728];

// -------------------- helpers --------------------
__device__ __forceinline__ uint32_t su32(const void* p) {
    uint32_t a;
    asm("{ .reg .u64 t; cvta.to.shared.u64 t, %1; cvt.u32.u64 %0, t; }" : "=r"(a) : "l"(p));
    return a;
}
__device__ __forceinline__ float ex2f(float x) {
    float y;
    asm("ex2.approx.f32 %0, %1;" : "=f"(y) : "f"(x));
    return y;
}
// f32 -> f16 hi/lo split of a float4: hp = hi halves, lp = lo halves
__device__ __forceinline__ void h2split(float4 v, uint2& hp, uint2& lp) {
    __half2 h0 = __floats2half2_rn(v.x, v.y);
    __half2 h1 = __floats2half2_rn(v.z, v.w);
    float2 f0 = __half22float2(h0), f1 = __half22float2(h1);
    __half2 l0 = __floats2half2_rn(v.x - f0.x, v.y - f0.y);
    __half2 l1 = __floats2half2_rn(v.z - f1.x, v.w - f1.y);
    hp.x = *(uint32_t*)&h0; hp.y = *(uint32_t*)&h1;
    lp.x = *(uint32_t*)&l0; lp.y = *(uint32_t*)&l1;
}
__device__ __forceinline__ void mma_f16(float* c, const uint32_t* a, const uint32_t* b) {
    asm volatile("mma.sync.aligned.m16n8k16.row.col.f32.f16.f16.f32 "
                 "{%0,%1,%2,%3}, {%4,%5,%6,%7}, {%8,%9}, {%0,%1,%2,%3};"
                 : "+f"(c[0]), "+f"(c[1]), "+f"(c[2]), "+f"(c[3])
                 : "r"(a[0]), "r"(a[1]), "r"(a[2]), "r"(a[3]), "r"(b[0]), "r"(b[1]));
}
__device__ __forceinline__ void ldmA(uint32_t* r, uint32_t addr) {
    asm volatile("ldmatrix.sync.aligned.m8n8.x4.shared.b16 {%0,%1,%2,%3}, [%4];"
                 : "=r"(r[0]), "=r"(r[1]), "=r"(r[2]), "=r"(r[3]) : "r"(addr));
}
// trans x4: two (k16,n8) B fragments (adjacent 8-col groups) in one op
__device__ __forceinline__ void ldmB4(uint32_t* r, uint32_t addr) {
    asm volatile("ldmatrix.sync.aligned.m8n8.x4.trans.shared.b16 {%0,%1,%2,%3}, [%4];"
                 : "=r"(r[0]), "=r"(r[1]), "=r"(r[2]), "=r"(r[3]) : "r"(addr));
}
// non-trans x4: two (n8,k16) B fragments (adjacent 8-key groups) in one op
__device__ __forceinline__ void ldmBn4(uint32_t* r, uint32_t addr) {
    asm volatile("ldmatrix.sync.aligned.m8n8.x4.shared.b16 {%0,%1,%2,%3}, [%4];"
                 : "=r"(r[0]), "=r"(r[1]), "=r"(r[2]), "=r"(r[3]) : "r"(addr));
}

// ==================== kernel 1: fused QKV projections ====================
__global__ __launch_bounds__(256) void proj_fused_kernel(
    const float* __restrict__ q, const float* __restrict__ k, const float* __restrict__ v,
    const float* __restrict__ Wq, const float* __restrict__ bq,
    const float* __restrict__ Wk, const float* __restrict__ bk,
    const float* __restrict__ Wv, const float* __restrict__ bv,
    float* __restrict__ Qh, float* __restrict__ Kh, float* __restrict__ Vh) {
    __shared__ float Xs[64][65];
    __shared__ float Ws[64][65];
    int rt = blockIdx.x, head = blockIdx.y, z = blockIdx.z, tid = threadIdx.x;
    const float* X = (z == 0) ? q : (z == 1) ? k : v;
    const float* W = (z == 0) ? Wq : (z == 1) ? Wk : Wv;
    const float* bias = (z == 0) ? bq : (z == 1) ? bk : bv;
    float* Out = (z == 0) ? Qh : (z == 1) ? Kh : Vh;

#pragma unroll
    for (int t = 0; t < 4; t++) {
        int f = tid + t * 256;
        int r = f >> 4, c = (f & 15) << 2;
        float4 xv = *(const float4*)(X + (size_t)(rt * 64 + r) * DIN + c);
        Xs[r][c] = xv.x; Xs[r][c + 1] = xv.y; Xs[r][c + 2] = xv.z; Xs[r][c + 3] = xv.w;
        float4 wv = *(const float4*)(W + (size_t)r * HD + head * 64 + c);
        Ws[r][c] = wv.x; Ws[r][c + 1] = wv.y; Ws[r][c + 2] = wv.z; Ws[r][c + 3] = wv.w;
    }
    __syncthreads();
    int ty = tid >> 4, tx = tid & 15;
    int r0 = ty * 4, c0 = tx * 4;
    float acc[4][4] = {};
#pragma unroll
    for (int kk = 0; kk < 64; kk++) {
        float a[4], b[4];
#pragma unroll
        for (int i = 0; i < 4; i++) a[i] = Xs[r0 + i][kk];
#pragma unroll
        for (int j = 0; j < 4; j++) b[j] = Ws[kk][c0 + j];
#pragma unroll
        for (int i = 0; i < 4; i++)
#pragma unroll
            for (int j = 0; j < 4; j++) acc[i][j] = fmaf(a[i], b[j], acc[i][j]);
    }
    int bb = (rt * 64) / SEQ;
    int nbase = rt * 64 - bb * SEQ;
    float bv4[4];
#pragma unroll
    for (int j = 0; j < 4; j++) bv4[j] = bias[head * 64 + c0 + j];
#pragma unroll
    for (int i = 0; i < 4; i++) {
        float4 o;
        o.x = acc[i][0] + bv4[0]; o.y = acc[i][1] + bv4[1];
        o.z = acc[i][2] + bv4[2]; o.w = acc[i][3] + bv4[3];
        size_t row = (size_t)(head * BATCH + bb) * SEQ + nbase + r0 + i;
        *(float4*)(Out + row * DHEAD + c0) = o;
    }
}

// ==================== kernel 2: scores via f16-3x m16n8k16 (x4 B-loads) ====================
// 512 threads, 16 warps; warp = (wr 0..3 rowgroup of 32, wq 0..3 colquad of 32)
#define SC_QH 0
#define SC_QL 18432
#define SC_KB0 36864
#define SC_KBSTRIDE 36864
#define SC_STATS 110592
#define SC_SMEM_BYTES 114688

__global__ __launch_bounds__(512, 1) void scores_mma_kernel(float* __restrict__ attn) {
    extern __shared__ char smc[];
    uint32_t sb = su32(smc);

    int tid = threadIdx.x, lane = tid & 31, w = tid >> 5;
    int g = lane >> 2, tg = lane & 3;
    int wr = w & 3, wq = w >> 2;
    int hb = blockIdx.x, qt = blockIdx.y;
    int r1 = wr * 32 + g;

    // ---- load Q (log2 domain, f16 hi/lo split), row-major [row][dim] stride 72 halves ----
    const float* Qp = g_Qh + ((size_t)hb * SEQ + qt * 128) * DHEAD;
#pragma unroll
    for (int t = 0; t < 4; t++) {
        int f = tid + t * 512;
        int r = f >> 4, c = (f & 15) << 2;
        float4 v = *(const float4*)(Qp + (size_t)r * DHEAD + c);
        v.x *= SCL; v.y *= SCL; v.z *= SCL; v.w *= SCL;
        uint2 hp, lp;
        h2split(v, hp, lp);
        *(uint2*)(smc + SC_QH + (r * 72 + c) * 2) = hp;
        *(uint2*)(smc + SC_QL + (r * 72 + c) * 2) = lp;
    }
    // ---- prologue: K tile 0 -> buf0 ----
    {
        const float* Kp = g_Kh + ((size_t)hb * SEQ) * DHEAD;
#pragma unroll
        for (int t = 0; t < 4; t++) {
            int f = tid + t * 512;
            int r = f >> 4, c = (f & 15) << 2;
            float4 v = *(const float4*)(Kp + (size_t)r * DHEAD + c);
            uint2 hp, lp;
            h2split(v, hp, lp);
            *(uint2*)(smc + SC_KB0 + (r * 72 + c) * 2) = hp;
            *(uint2*)(smc + SC_KB0 + 18432 + (r * 72 + c) * 2) = lp;
        }
    }
    __syncthreads();

    float mA[2] = {-1e30f, -1e30f}, lA[2] = {0.f, 0.f};
    float mB[2] = {-1e30f, -1e30f}, lB[2] = {0.f, 0.f};
    float* Tbase = attn + (size_t)hb * SEQ * SEQ + (size_t)(qt * 128) * SEQ;

    int arow = (lane & 15);
    int acl = ((lane >> 4) & 1) * 8;
    // x4 non-trans B addressing (verified R11): lanes 0-7 frag0 keys d0-7,
    // 8-15 frag0 keys d8-15, 16-23 frag1 keys+8 d0-7, 24-31 frag1 keys+8 d8-15
    int bkey4 = wq * 32 + (lane & 7) + ((lane >> 4) & 1) * 8;
    int bdim4 = ((lane >> 3) & 1) * 8;

    for (int kt = 0; kt < 16; kt++) {
        float4 pre[4];
        if (kt < 15) {
            const float* Kp = g_Kh + ((size_t)hb * SEQ + (kt + 1) * 128) * DHEAD;
#pragma unroll
            for (int t = 0; t < 4; t++) {
                int f = tid + t * 512;
                int r = f >> 4, c = (f & 15) << 2;
                pre[t] = *(const float4*)(Kp + (size_t)r * DHEAD + c);
            }
        }
        uint32_t kbH = sb + SC_KB0 + (kt & 1) * SC_KBSTRIDE;
        uint32_t kbL = kbH + 18432;

        float C[2][4][4];
#pragma unroll
        for (int mt = 0; mt < 2; mt++)
#pragma unroll
            for (int j = 0; j < 4; j++) { C[mt][j][0] = C[mt][j][1] = C[mt][j][2] = C[mt][j][3] = 0.f; }

#pragma unroll
        for (int ks = 0; ks < 4; ks++) {
            uint32_t aH[2][4], aL[2][4];
#pragma unroll
            for (int mt = 0; mt < 2; mt++) {
                uint32_t off = (uint32_t)(((wr * 32 + mt * 16 + arow) * 72 + ks * 16 + acl) * 2);
                ldmA(aH[mt], sb + SC_QH + off);
                ldmA(aL[mt], sb + SC_QL + off);
            }
#pragma unroll
            for (int jp = 0; jp < 2; jp++) {
                uint32_t boff = (uint32_t)(((bkey4 + jp * 16) * 72 + ks * 16 + bdim4) * 2);
                uint32_t b4H[4], b4L[4];
                ldmBn4(b4H, kbH + boff);
                ldmBn4(b4L, kbL + boff);
#pragma unroll
                for (int jj = 0; jj < 2; jj++)
#pragma unroll
                    for (int mt = 0; mt < 2; mt++) {
                        float* Cp = C[mt][jp * 2 + jj];
                        mma_f16(Cp, aH[mt], b4H + jj * 2);
                        mma_f16(Cp, aH[mt], b4L + jj * 2);
                        mma_f16(Cp, aL[mt], b4H + jj * 2);
                    }
            }
        }

        // online partial stats over this warp's 32 columns
#pragma unroll
        for (int mt = 0; mt < 2; mt++) {
            float mxa = C[mt][0][0], mxb = C[mt][0][2];
#pragma unroll
            for (int j = 0; j < 4; j++) {
                mxa = fmaxf(mxa, fmaxf(C[mt][j][0], C[mt][j][1]));
                mxb = fmaxf(mxb, fmaxf(C[mt][j][2], C[mt][j][3]));
            }
            mxa = fmaxf(mxa, __shfl_xor_sync(0xffffffffu, mxa, 1));
            mxa = fmaxf(mxa, __shfl_xor_sync(0xffffffffu, mxa, 2));
            mxb = fmaxf(mxb, __shfl_xor_sync(0xffffffffu, mxb, 1));
            mxb = fmaxf(mxb, __shfl_xor_sync(0xffffffffu, mxb, 2));
            float M1 = fmaxf(mA[mt], mxa), M2 = fmaxf(mB[mt], mxb);
            float sa = 0.f, sb2 = 0.f;
#pragma unroll
            for (int j = 0; j < 4; j++) {
                sa  += ex2f(C[mt][j][0] - M1) + ex2f(C[mt][j][1] - M1);
                sb2 += ex2f(C[mt][j][2] - M2) + ex2f(C[mt][j][3] - M2);
            }
            sa  += __shfl_xor_sync(0xffffffffu, sa, 1);
            sa  += __shfl_xor_sync(0xffffffffu, sa, 2);
            sb2 += __shfl_xor_sync(0xffffffffu, sb2, 1);
            sb2 += __shfl_xor_sync(0xffffffffu, sb2, 2);
            lA[mt] = lA[mt] * ex2f(mA[mt] - M1) + sa;  mA[mt] = M1;
            lB[mt] = lB[mt] * ex2f(mB[mt] - M2) + sb2; mB[mt] = M2;
        }

        // store raw log2-domain scores
#pragma unroll
        for (int mt = 0; mt < 2; mt++) {
            int rr = r1 + mt * 16;
            float* p1 = Tbase + (size_t)rr * SEQ + kt * 128 + wq * 32 + 2 * tg;
            float* p2 = p1 + (size_t)8 * SEQ;
#pragma unroll
            for (int j = 0; j < 4; j++) {
                *(float2*)(p1 + j * 8) = make_float2(C[mt][j][0], C[mt][j][1]);
                *(float2*)(p2 + j * 8) = make_float2(C[mt][j][2], C[mt][j][3]);
            }
        }

        if (kt < 15) {
            char* kb = smc + SC_KB0 + ((kt + 1) & 1) * SC_KBSTRIDE;
#pragma unroll
            for (int t = 0; t < 4; t++) {
                int f = tid + t * 512;
                int r = f >> 4, c = (f & 15) << 2;
                uint2 hp, lp;
                h2split(pre[t], hp, lp);
                *(uint2*)(kb + (r * 72 + c) * 2) = hp;
                *(uint2*)(kb + 18432 + (r * 72 + c) * 2) = lp;
            }
        }
        __syncthreads();
    }

    // combine 4 column-quad partials per row
    float* smm = (float*)(smc + SC_STATS);
    float* sml = smm + 512;
    if (tg == 0) {
#pragma unroll
        for (int mt = 0; mt < 2; mt++) {
            int rr = r1 + mt * 16;
            smm[wq * 128 + rr] = mA[mt];      sml[wq * 128 + rr] = lA[mt];
            smm[wq * 128 + rr + 8] = mB[mt];  sml[wq * 128 + rr + 8] = lB[mt];
        }
    }
    __syncthreads();
    if (tid < 128) {
        float M = smm[tid];
#pragma unroll
        for (int qd = 1; qd < 4; qd++) M = fmaxf(M, smm[qd * 128 + tid]);
        float L = 0.f;
#pragma unroll
        for (int qd = 0; qd < 4; qd++) L += sml[qd * 128 + tid] * ex2f(smm[qd * 128 + tid] - M);
        int base = hb * SEQ + qt * 128;
        g_m[base + tid] = M;
        g_l[base + tid] = L;
    }
}

// ==================== kernel 3: normalize + PV via f16-3x (R10 tiling, x4 B-loads) ====================
// 512 threads; double-buffered smem; warp = (wr 0..7 rows of 16, wc 0..1 col half of 32)
#define PV_PBUF 55296
#define PV_STAT 110592
#define PV_SMEM_BYTES 111616

__global__ __launch_bounds__(512, 1) void pv_mma_kernel(float* __restrict__ attn) {
    extern __shared__ char smc[];
    uint32_t sb = su32(smc);
    float* msm  = (float*)(smc + PV_STAT);
    float* ilsm = (float*)(smc + PV_STAT + 512);

    int tid = threadIdx.x, lane = tid & 31, w = tid >> 5;
    int g = lane >> 2, tg = lane & 3;
    int wr = w & 7, wc = w >> 3;
    int hb = blockIdx.x, qt = blockIdx.y;

    if (tid < 128) {
        msm[tid] = g_m[hb * SEQ + qt * 128 + tid];
        ilsm[tid] = 1.0f / g_l[hb * SEQ + qt * 128 + tid];
    }
    __syncthreads();

    float* arow = attn + (size_t)hb * SEQ * SEQ + (size_t)(qt * 128) * SEQ;
    float C[4][4];
#pragma unroll
    for (int j = 0; j < 4; j++) { C[j][0] = C[j][1] = C[j][2] = C[j][3] = 0.f; }

    float4 aR[4], vR[2];
    // prologue: load + process chunk 0 into buf 0
    {
        const float* Vp = g_Vh + ((size_t)hb * SEQ) * DHEAD;
#pragma unroll
        for (int t = 0; t < 4; t++) {
            int f = tid + t * 512;
            int r = f >> 4, c = (f & 15) << 2;
            aR[t] = *(const float4*)(arow + (size_t)r * SEQ + c);
        }
#pragma unroll
        for (int t = 0; t < 2; t++) {
            int f = tid + t * 512;
            int kk = f >> 4, dd = (f & 15) << 2;
            vR[t] = *(const float4*)(Vp + (size_t)kk * DHEAD + dd);
        }
        char* bufc = smc;
#pragma unroll
        for (int t = 0; t < 4; t++) {
            int f = tid + t * 512;
            int r = f >> 4, c = (f & 15) << 2;
            float4 v = aR[t];
            float mm = msm[r], il = ilsm[r];
            v.x = ex2f(v.x - mm) * il; v.y = ex2f(v.y - mm) * il;
            v.z = ex2f(v.z - mm) * il; v.w = ex2f(v.w - mm) * il;
            *(float4*)(arow + (size_t)r * SEQ + c) = v;
            uint2 hp, lp;
            h2split(v, hp, lp);
            *(uint2*)(bufc + (r * 72 + c) * 2) = hp;
            *(uint2*)(bufc + 18432 + (r * 72 + c) * 2) = lp;
        }
#pragma unroll
        for (int t = 0; t < 2; t++) {
            int f = tid + t * 512;
            int kk = f >> 4, dd = (f & 15) << 2;
            uint2 hp, lp;
            h2split(vR[t], hp, lp);
            *(uint2*)(bufc + 36864 + (kk * 72 + dd) * 2) = hp;
            *(uint2*)(bufc + 46080 + (kk * 72 + dd) * 2) = lp;
        }
    }
    __syncthreads();

    int arw = wr * 16 + (lane & 15);
    int acl = ((lane >> 4) & 1) * 8;
    int brow4 = (lane & 15);
    int bcol4 = wc * 32 + ((lane >> 4) & 1) * 8;

    for (int kc = 0; kc < 32; kc++) {
        int b = kc & 1;
        if (kc < 31) {
            const float* Vp = g_Vh + ((size_t)hb * SEQ + (kc + 1) * 64) * DHEAD;
#pragma unroll
            for (int t = 0; t < 4; t++) {
                int f = tid + t * 512;
                int r = f >> 4, c = (f & 15) << 2;
                aR[t] = *(const float4*)(arow + (size_t)r * SEQ + (kc + 1) * 64 + c);
            }
#pragma unroll
            for (int t = 0; t < 2; t++) {
                int f = tid + t * 512;
                int kk = f >> 4, dd = (f & 15) << 2;
                vR[t] = *(const float4*)(Vp + (size_t)kk * DHEAD + dd);
            }
        }
        // mma from buffer b
        uint32_t bufb = sb + b * PV_PBUF;
        uint32_t aHf[4][4], aLf[4][4];
#pragma unroll
        for (int s = 0; s < 4; s++) {
            uint32_t off = (uint32_t)((arw * 72 + s * 16 + acl) * 2);
            ldmA(aHf[s], bufb + off);
            ldmA(aLf[s], bufb + 18432 + off);
        }
#pragma unroll
        for (int jp = 0; jp < 2; jp++) {
#pragma unroll
            for (int s = 0; s < 4; s++) {
                uint32_t boff = (uint32_t)(((s * 16 + brow4) * 72 + bcol4 + jp * 16) * 2);
                uint32_t b4H[4], b4L[4];
                ldmB4(b4H, bufb + 36864 + boff);
                ldmB4(b4L, bufb + 46080 + boff);
#pragma unroll
                for (int jj = 0; jj < 2; jj++) {
                    float* Cp = C[jp * 2 + jj];
                    mma_f16(Cp, aHf[s], b4H + jj * 2);
                    mma_f16(Cp, aHf[s], b4L + jj * 2);
                    mma_f16(Cp, aLf[s], b4H + jj * 2);
                }
            }
        }
        if (kc < 31) {
            char* bufc = smc + (b ^ 1) * PV_PBUF;
#pragma unroll
            for (int t = 0; t < 4; t++) {
                int f = tid + t * 512;
                int r = f >> 4, c = (f & 15) << 2;
                float4 v = aR[t];
                float mm = msm[r], il = ilsm[r];
                v.x = ex2f(v.x - mm) * il; v.y = ex2f(v.y - mm) * il;
                v.z = ex2f(v.z - mm) * il; v.w = ex2f(v.w - mm) * il;
                *(float4*)(arow + (size_t)r * SEQ + (kc + 1) * 64 + c) = v;
                uint2 hp, lp;
                h2split(v, hp, lp);
                *(uint2*)(bufc + (r * 72 + c) * 2) = hp;
                *(uint2*)(bufc + 18432 + (r * 72 + c) * 2) = lp;
            }
#pragma unroll
            for (int t = 0; t < 2; t++) {
                int f = tid + t * 512;
                int kk = f >> 4, dd = (f & 15) << 2;
                uint2 hp, lp;
                h2split(vR[t], hp, lp);
                *(uint2*)(bufc + 36864 + (kk * 72 + dd) * 2) = hp;
                *(uint2*)(bufc + 46080 + (kk * 72 + dd) * 2) = lp;
            }
        }
        __syncthreads();
    }

    int h = hb >> 1, bb = hb & 1;
    int r1 = wr * 16 + g;
    float* o1 = g_oh + ((size_t)(bb * SEQ + qt * 128 + r1)) * HD + h * 64 + wc * 32 + 2 * tg;
    float* o2 = o1 + 8 * HD;
#pragma unroll
    for (int j = 0; j < 4; j++) {
        *(float2*)(o1 + j * 8) = make_float2(C[j][0], C[j][1]);
        *(float2*)(o2 + j * 8) = make_float2(C[j][2], C[j][3]);
    }
}

// ==================== kernel 4: out projection (R10 tiling, x4 B-loads) ====================
// 512 threads; double-buffered; warp = (wr 0..7 rows of 16, wc 0..1 col half of 64)
#define OP_PBUF 71680
#define OP_SMEM_BYTES 143360

__global__ __launch_bounds__(512, 1) void oproj_mma_kernel(
    const float* __restrict__ Wo, const float* __restrict__ bo, float* __restrict__ out) {
    extern __shared__ char smc[];
    uint32_t sb = su32(smc);

    int tid = threadIdx.x, lane = tid & 31, w = tid >> 5;
    int g = lane >> 2, tg = lane & 3;
    int wr = w & 7, wc = w >> 3;
    int rt = blockIdx.x, ct = blockIdx.y;

    float C[8][4];
#pragma unroll
    for (int j = 0; j < 8; j++) { C[j][0] = C[j][1] = C[j][2] = C[j][3] = 0.f; }

    float4 aR[4], bR[4];
    // prologue
    {
#pragma unroll
        for (int t = 0; t < 4; t++) {
            int f = tid + t * 512;
            int r = f >> 4, c = (f & 15) << 2;
            aR[t] = *(const float4*)(g_oh + (size_t)(rt * 128 + r) * HD + c);
        }
#pragma unroll
        for (int t = 0; t < 4; t++) {
            int f = tid + t * 512;
            int kk = f >> 5, nn = (f & 31) << 2;
            bR[t] = *(const float4*)(Wo + (size_t)kk * DO + ct * 128 + nn);
        }
        char* bufc = smc;
#pragma unroll
        for (int t = 0; t < 4; t++) {
            int f = tid + t * 512;
            int r = f >> 4, c = (f & 15) << 2;
            uint2 hp, lp;
            h2split(aR[t], hp, lp);
            *(uint2*)(bufc + (r * 72 + c) * 2) = hp;
            *(uint2*)(bufc + 18432 + (r * 72 + c) * 2) = lp;
        }
#pragma unroll
        for (int t = 0; t < 4; t++) {
            int f = tid + t * 512;
            int kk = f >> 5, nn = (f & 31) << 2;
            uint2 hp, lp;
            h2split(bR[t], hp, lp);
            *(uint2*)(bufc + 36864 + (kk * 136 + nn) * 2) = hp;
            *(uint2*)(bufc + 54272 + (kk * 136 + nn) * 2) = lp;
        }
    }
    __syncthreads();

    int arw = wr * 16 + (lane & 15);
    int acl = ((lane >> 4) & 1) * 8;
    int brow4 = (lane & 15);
    int bcol4 = wc * 64 + ((lane >> 4) & 1) * 8;

    for (int kc = 0; kc < 16; kc++) {
        int b = kc & 1;
        if (kc < 15) {
#pragma unroll
            for (int t = 0; t < 4; t++) {
                int f = tid + t * 512;
                int r = f >> 4, c = (f & 15) << 2;
                aR[t] = *(const float4*)(g_oh + (size_t)(rt * 128 + r) * HD + (kc + 1) * 64 + c);
            }
#pragma unroll
            for (int t = 0; t < 4; t++) {
                int f = tid + t * 512;
                int kk = f >> 5, nn = (f & 31) << 2;
                bR[t] = *(const float4*)(Wo + (size_t)((kc + 1) * 64 + kk) * DO + ct * 128 + nn);
            }
        }
        uint32_t bufb = sb + b * OP_PBUF;
        uint32_t aHf[4][4], aLf[4][4];
#pragma unroll
        for (int s = 0; s < 4; s++) {
            uint32_t off = (uint32_t)((arw * 72 + s * 16 + acl) * 2);
            ldmA(aHf[s], bufb + off);
            ldmA(aLf[s], bufb + 18432 + off);
        }
#pragma unroll
        for (int jp = 0; jp < 4; jp++) {
#pragma unroll
            for (int s = 0; s < 4; s++) {
                uint32_t boff = (uint32_t)(((s * 16 + brow4) * 136 + bcol4 + jp * 16) * 2);
                uint32_t b4H[4], b4L[4];
                ldmB4(b4H, bufb + 36864 + boff);
                ldmB4(b4L, bufb + 54272 + boff);
#pragma unroll
                for (int jj = 0; jj < 2; jj++) {
                    float* Cp = C[jp * 2 + jj];
                    mma_f16(Cp, aHf[s], b4H + jj * 2);
                    mma_f16(Cp, aHf[s], b4L + jj * 2);
                    mma_f16(Cp, aLf[s], b4H + jj * 2);
                }
            }
        }
        if (kc < 15) {
            char* bufc = smc + (b ^ 1) * OP_PBUF;
#pragma unroll
            for (int t = 0; t < 4; t++) {
                int f = tid + t * 512;
                int r = f >> 4, c = (f & 15) << 2;
                uint2 hp, lp;
                h2split(aR[t], hp, lp);
                *(uint2*)(bufc + (r * 72 + c) * 2) = hp;
                *(uint2*)(bufc + 18432 + (r * 72 + c) * 2) = lp;
            }
#pragma unroll
            for (int t = 0; t < 4; t++) {
                int f = tid + t * 512;
                int kk = f >> 5, nn = (f & 31) << 2;
                uint2 hp, lp;
                h2split(bR[t], hp, lp);
                *(uint2*)(bufc + 36864 + (kk * 136 + nn) * 2) = hp;
                *(uint2*)(bufc + 54272 + (kk * 136 + nn) * 2) = lp;
            }
        }
        __syncthreads();
    }

    int r1 = wr * 16 + g;
    const float* bp = bo + ct * 128 + wc * 64;
    float* o1 = out + (size_t)(rt * 128 + r1) * DO + ct * 128 + wc * 64 + 2 * tg;
    float* o2 = o1 + 8 * DO;
#pragma unroll
    for (int j = 0; j < 8; j++) {
        int cc = j * 8 + 2 * tg;
        *(float2*)(o1 + j * 8) = make_float2(C[j][0] + bp[cc], C[j][1] + bp[cc + 1]);
        *(float2*)(o2 + j * 8) = make_float2(C[j][2] + bp[cc], C[j][3] + bp[cc + 1]);
    }
}

// ==================== launch ====================
extern "C" void kernel_launch(void* const* d_in, const int* in_sizes, int n_in,
                              void* d_out, int out_size) {
    const float* q  = (const float*)d_in[0];
    const float* k  = (const float*)d_in[1];
    const float* v  = (const float*)d_in[2];
    const float* Wq = (const float*)d_in[3];
    const float* bq = (const float*)d_in[4];
    const float* Wk = (const float*)d_in[5];
    const float* bk = (const float*)d_in[6];
    const float* Wv = (const float*)d_in[7];
    const float* bv = (const float*)d_in[8];
    const float* Wo = (const float*)d_in[9];
    const float* bo = (const float*)d_in[10];
    (void)in_sizes; (void)n_in;

    long long osz = (long long)out_size;
    float* attn = nullptr;
    float* out  = nullptr;
    if (osz >= ATTN_ELEMS + OUT_ELEMS) {
        attn = (float*)d_out;
        out  = (float*)d_out + ATTN_ELEMS;
    } else if (osz >= ATTN_ELEMS) {
        attn = (float*)d_out;
    } else {
        out = (float*)d_out;
    }
    if (!attn) cudaGetSymbolAddress((void**)&attn, g_attn_fb);

    float *Qh, *Kh, *Vh;
    cudaGetSymbolAddress((void**)&Qh, g_Qh);
    cudaGetSymbolAddress((void**)&Kh, g_Kh);
    cudaGetSymbolAddress((void**)&Vh, g_Vh);

    cudaFuncSetAttribute(scores_mma_kernel, cudaFuncAttributeMaxDynamicSharedMemorySize, SC_SMEM_BYTES);
    cudaFuncSetAttribute(pv_mma_kernel, cudaFuncAttributeMaxDynamicSharedMemorySize, PV_SMEM_BYTES);
    cudaFuncSetAttribute(oproj_mma_kernel, cudaFuncAttributeMaxDynamicSharedMemorySize, OP_SMEM_BYTES);

    proj_fused_kernel<<<dim3(64, 16, 3), 256>>>(q, k, v, Wq, bq, Wk, bk, Wv, bv, Qh, Kh, Vh);
    scores_mma_kernel<<<dim3(HB, 16), 512, SC_SMEM_BYTES>>>(attn);
    pv_mma_kernel<<<dim3(HB, 16), 512, PV_SMEM_BYTES>>>(attn);
    if (out) oproj_mma_kernel<<<dim3(32, 8), 512, OP_SMEM_BYTES>>>(Wo, bo, out);
}

// round 16
// speedup vs baseline: 1.6595x; 1.0457x over previous
#include <cuda_runtime.h>
#include <cuda_fp16.h>
#include <cstdint>

// Problem constants
#define BATCH  2
#define SEQ    2048
#define DIN    64
#define NHEAD  16
#define DHEAD  64
#define HB     32
#define HD     1024
#define NROWS  4096
#define DO     1024

#define ATTN_ELEMS 134217728LL
#define OUT_ELEMS  4194304LL

// fold 1/sqrt(64) and log2(e): scores kept in log2 domain
#define SCL (0.125f * 1.4426950408889634f)

// -------------------- scratch --------------------
__device__ float g_Qh[HB * SEQ * DHEAD];
__device__ float g_Kh[HB * SEQ * DHEAD];
__device__ float g_Vh[HB * SEQ * DHEAD];
__device__ float g_m[HB * SEQ];
__device__ float g_l[HB * SEQ];
__device__ float g_oh[NROWS * HD];
__device__ float g_attn_fb[134217728];

// -------------------- helpers --------------------
__device__ __forceinline__ uint32_t su32(const void* p) {
    uint32_t a;
    asm("{ .reg .u64 t; cvta.to.shared.u64 t, %1; cvt.u32.u64 %0, t; }" : "=r"(a) : "l"(p));
    return a;
}
__device__ __forceinline__ float ex2f(float x) {
    float y;
    asm("ex2.approx.f32 %0, %1;" : "=f"(y) : "f"(x));
    return y;
}
// f32 -> f16 hi/lo split of a float4: hp = hi halves, lp = lo halves
__device__ __forceinline__ void h2split(float4 v, uint2& hp, uint2& lp) {
    __half2 h0 = __floats2half2_rn(v.x, v.y);
    __half2 h1 = __floats2half2_rn(v.z, v.w);
    float2 f0 = __half22float2(h0), f1 = __half22float2(h1);
    __half2 l0 = __floats2half2_rn(v.x - f0.x, v.y - f0.y);
    __half2 l1 = __floats2half2_rn(v.z - f1.x, v.w - f1.y);
    hp.x = *(uint32_t*)&h0; hp.y = *(uint32_t*)&h1;
    lp.x = *(uint32_t*)&l0; lp.y = *(uint32_t*)&l1;
}
// f32 -> f16 hi only
__device__ __forceinline__ uint2 h2hi(float4 v) {
    __half2 h0 = __floats2half2_rn(v.x, v.y);
    __half2 h1 = __floats2half2_rn(v.z, v.w);
    uint2 hp;
    hp.x = *(uint32_t*)&h0; hp.y = *(uint32_t*)&h1;
    return hp;
}
__device__ __forceinline__ void mma_f16(float* c, const uint32_t* a, const uint32_t* b) {
    asm volatile("mma.sync.aligned.m16n8k16.row.col.f32.f16.f16.f32 "
                 "{%0,%1,%2,%3}, {%4,%5,%6,%7}, {%8,%9}, {%0,%1,%2,%3};"
                 : "+f"(c[0]), "+f"(c[1]), "+f"(c[2]), "+f"(c[3])
                 : "r"(a[0]), "r"(a[1]), "r"(a[2]), "r"(a[3]), "r"(b[0]), "r"(b[1]));
}
__device__ __forceinline__ void ldmA(uint32_t* r, uint32_t addr) {
    asm volatile("ldmatrix.sync.aligned.m8n8.x4.shared.b16 {%0,%1,%2,%3}, [%4];"
                 : "=r"(r[0]), "=r"(r[1]), "=r"(r[2]), "=r"(r[3]) : "r"(addr));
}
// trans x4: two (k16,n8) B fragments (adjacent 8-col groups) in one op
__device__ __forceinline__ void ldmB4(uint32_t* r, uint32_t addr) {
    asm volatile("ldmatrix.sync.aligned.m8n8.x4.trans.shared.b16 {%0,%1,%2,%3}, [%4];"
                 : "=r"(r[0]), "=r"(r[1]), "=r"(r[2]), "=r"(r[3]) : "r"(addr));
}
// non-trans x4: two (n8,k16) B fragments (adjacent 8-key groups) in one op
__device__ __forceinline__ void ldmBn4(uint32_t* r, uint32_t addr) {
    asm volatile("ldmatrix.sync.aligned.m8n8.x4.shared.b16 {%0,%1,%2,%3}, [%4];"
                 : "=r"(r[0]), "=r"(r[1]), "=r"(r[2]), "=r"(r[3]) : "r"(addr));
}

// ==================== kernel 1: fused QKV projections ====================
__global__ __launch_bounds__(256) void proj_fused_kernel(
    const float* __restrict__ q, const float* __restrict__ k, const float* __restrict__ v,
    const float* __restrict__ Wq, const float* __restrict__ bq,
    const float* __restrict__ Wk, const float* __restrict__ bk,
    const float* __restrict__ Wv, const float* __restrict__ bv,
    float* __restrict__ Qh, float* __restrict__ Kh, float* __restrict__ Vh) {
    __shared__ float Xs[64][65];
    __shared__ float Ws[64][65];
    int rt = blockIdx.x, head = blockIdx.y, z = blockIdx.z, tid = threadIdx.x;
    const float* X = (z == 0) ? q : (z == 1) ? k : v;
    const float* W = (z == 0) ? Wq : (z == 1) ? Wk : Wv;
    const float* bias = (z == 0) ? bq : (z == 1) ? bk : bv;
    float* Out = (z == 0) ? Qh : (z == 1) ? Kh : Vh;

#pragma unroll
    for (int t = 0; t < 4; t++) {
        int f = tid + t * 256;
        int r = f >> 4, c = (f & 15) << 2;
        float4 xv = *(const float4*)(X + (size_t)(rt * 64 + r) * DIN + c);
        Xs[r][c] = xv.x; Xs[r][c + 1] = xv.y; Xs[r][c + 2] = xv.z; Xs[r][c + 3] = xv.w;
        float4 wv = *(const float4*)(W + (size_t)r * HD + head * 64 + c);
        Ws[r][c] = wv.x; Ws[r][c + 1] = wv.y; Ws[r][c + 2] = wv.z; Ws[r][c + 3] = wv.w;
    }
    __syncthreads();
    int ty = tid >> 4, tx = tid & 15;
    int r0 = ty * 4, c0 = tx * 4;
    float acc[4][4] = {};
#pragma unroll
    for (int kk = 0; kk < 64; kk++) {
        float a[4], b[4];
#pragma unroll
        for (int i = 0; i < 4; i++) a[i] = Xs[r0 + i][kk];
#pragma unroll
        for (int j = 0; j < 4; j++) b[j] = Ws[kk][c0 + j];
#pragma unroll
        for (int i = 0; i < 4; i++)
#pragma unroll
            for (int j = 0; j < 4; j++) acc[i][j] = fmaf(a[i], b[j], acc[i][j]);
    }
    int bb = (rt * 64) / SEQ;
    int nbase = rt * 64 - bb * SEQ;
    float bv4[4];
#pragma unroll
    for (int j = 0; j < 4; j++) bv4[j] = bias[head * 64 + c0 + j];
#pragma unroll
    for (int i = 0; i < 4; i++) {
        float4 o;
        o.x = acc[i][0] + bv4[0]; o.y = acc[i][1] + bv4[1];
        o.z = acc[i][2] + bv4[2]; o.w = acc[i][3] + bv4[3];
        size_t row = (size_t)(head * BATCH + bb) * SEQ + nbase + r0 + i;
        *(float4*)(Out + row * DHEAD + c0) = o;
    }
}

// ==================== kernel 2: scores via f16-3x m16n8k16 (x4 B-loads) ====================
// 512 threads, 16 warps; warp = (wr 0..3 rowgroup of 32, wq 0..3 colquad of 32)
#define SC_QH 0
#define SC_QL 18432
#define SC_KB0 36864
#define SC_KBSTRIDE 36864
#define SC_STATS 110592
#define SC_SMEM_BYTES 114688

__global__ __launch_bounds__(512, 1) void scores_mma_kernel(float* __restrict__ attn) {
    extern __shared__ char smc[];
    uint32_t sb = su32(smc);

    int tid = threadIdx.x, lane = tid & 31, w = tid >> 5;
    int g = lane >> 2, tg = lane & 3;
    int wr = w & 3, wq = w >> 2;
    int hb = blockIdx.x, qt = blockIdx.y;
    int r1 = wr * 32 + g;

    // ---- load Q (log2 domain, f16 hi/lo split), row-major [row][dim] stride 72 halves ----
    const float* Qp = g_Qh + ((size_t)hb * SEQ + qt * 128) * DHEAD;
#pragma unroll
    for (int t = 0; t < 4; t++) {
        int f = tid + t * 512;
        int r = f >> 4, c = (f & 15) << 2;
        float4 v = *(const float4*)(Qp + (size_t)r * DHEAD + c);
        v.x *= SCL; v.y *= SCL; v.z *= SCL; v.w *= SCL;
        uint2 hp, lp;
        h2split(v, hp, lp);
        *(uint2*)(smc + SC_QH + (r * 72 + c) * 2) = hp;
        *(uint2*)(smc + SC_QL + (r * 72 + c) * 2) = lp;
    }
    // ---- prologue: K tile 0 -> buf0 ----
    {
        const float* Kp = g_Kh + ((size_t)hb * SEQ) * DHEAD;
#pragma unroll
        for (int t = 0; t < 4; t++) {
            int f = tid + t * 512;
            int r = f >> 4, c = (f & 15) << 2;
            float4 v = *(const float4*)(Kp + (size_t)r * DHEAD + c);
            uint2 hp, lp;
            h2split(v, hp, lp);
            *(uint2*)(smc + SC_KB0 + (r * 72 + c) * 2) = hp;
            *(uint2*)(smc + SC_KB0 + 18432 + (r * 72 + c) * 2) = lp;
        }
    }
    __syncthreads();

    float mA[2] = {-1e30f, -1e30f}, lA[2] = {0.f, 0.f};
    float mB[2] = {-1e30f, -1e30f}, lB[2] = {0.f, 0.f};
    float* Tbase = attn + (size_t)hb * SEQ * SEQ + (size_t)(qt * 128) * SEQ;

    int arow = (lane & 15);
    int acl = ((lane >> 4) & 1) * 8;
    // x4 non-trans B addressing
    int bkey4 = wq * 32 + (lane & 7) + ((lane >> 4) & 1) * 8;
    int bdim4 = ((lane >> 3) & 1) * 8;

    for (int kt = 0; kt < 16; kt++) {
        float4 pre[4];
        if (kt < 15) {
            const float* Kp = g_Kh + ((size_t)hb * SEQ + (kt + 1) * 128) * DHEAD;
#pragma unroll
            for (int t = 0; t < 4; t++) {
                int f = tid + t * 512;
                int r = f >> 4, c = (f & 15) << 2;
                pre[t] = *(const float4*)(Kp + (size_t)r * DHEAD + c);
            }
        }
        uint32_t kbH = sb + SC_KB0 + (kt & 1) * SC_KBSTRIDE;
        uint32_t kbL = kbH + 18432;

        float C[2][4][4];
#pragma unroll
        for (int mt = 0; mt < 2; mt++)
#pragma unroll
            for (int j = 0; j < 4; j++) { C[mt][j][0] = C[mt][j][1] = C[mt][j][2] = C[mt][j][3] = 0.f; }

#pragma unroll
        for (int ks = 0; ks < 4; ks++) {
            uint32_t aH[2][4], aL[2][4];
#pragma unroll
            for (int mt = 0; mt < 2; mt++) {
                uint32_t off = (uint32_t)(((wr * 32 + mt * 16 + arow) * 72 + ks * 16 + acl) * 2);
                ldmA(aH[mt], sb + SC_QH + off);
                ldmA(aL[mt], sb + SC_QL + off);
            }
#pragma unroll
            for (int jp = 0; jp < 2; jp++) {
                uint32_t boff = (uint32_t)(((bkey4 + jp * 16) * 72 + ks * 16 + bdim4) * 2);
                uint32_t b4H[4], b4L[4];
                ldmBn4(b4H, kbH + boff);
                ldmBn4(b4L, kbL + boff);
#pragma unroll
                for (int jj = 0; jj < 2; jj++)
#pragma unroll
                    for (int mt = 0; mt < 2; mt++) {
                        float* Cp = C[mt][jp * 2 + jj];
                        mma_f16(Cp, aH[mt], b4H + jj * 2);
                        mma_f16(Cp, aH[mt], b4L + jj * 2);
                        mma_f16(Cp, aL[mt], b4H + jj * 2);
                    }
            }
        }

        // online partial stats over this warp's 32 columns
#pragma unroll
        for (int mt = 0; mt < 2; mt++) {
            float mxa = C[mt][0][0], mxb = C[mt][0][2];
#pragma unroll
            for (int j = 0; j < 4; j++) {
                mxa = fmaxf(mxa, fmaxf(C[mt][j][0], C[mt][j][1]));
                mxb = fmaxf(mxb, fmaxf(C[mt][j][2], C[mt][j][3]));
            }
            mxa = fmaxf(mxa, __shfl_xor_sync(0xffffffffu, mxa, 1));
            mxa = fmaxf(mxa, __shfl_xor_sync(0xffffffffu, mxa, 2));
            mxb = fmaxf(mxb, __shfl_xor_sync(0xffffffffu, mxb, 1));
            mxb = fmaxf(mxb, __shfl_xor_sync(0xffffffffu, mxb, 2));
            float M1 = fmaxf(mA[mt], mxa), M2 = fmaxf(mB[mt], mxb);
            float sa = 0.f, sb2 = 0.f;
#pragma unroll
            for (int j = 0; j < 4; j++) {
                sa  += ex2f(C[mt][j][0] - M1) + ex2f(C[mt][j][1] - M1);
                sb2 += ex2f(C[mt][j][2] - M2) + ex2f(C[mt][j][3] - M2);
            }
            sa  += __shfl_xor_sync(0xffffffffu, sa, 1);
            sa  += __shfl_xor_sync(0xffffffffu, sa, 2);
            sb2 += __shfl_xor_sync(0xffffffffu, sb2, 1);
            sb2 += __shfl_xor_sync(0xffffffffu, sb2, 2);
            lA[mt] = lA[mt] * ex2f(mA[mt] - M1) + sa;  mA[mt] = M1;
            lB[mt] = lB[mt] * ex2f(mB[mt] - M2) + sb2; mB[mt] = M2;
        }

        // store raw log2-domain scores
#pragma unroll
        for (int mt = 0; mt < 2; mt++) {
            int rr = r1 + mt * 16;
            float* p1 = Tbase + (size_t)rr * SEQ + kt * 128 + wq * 32 + 2 * tg;
            float* p2 = p1 + (size_t)8 * SEQ;
#pragma unroll
            for (int j = 0; j < 4; j++) {
                *(float2*)(p1 + j * 8) = make_float2(C[mt][j][0], C[mt][j][1]);
                *(float2*)(p2 + j * 8) = make_float2(C[mt][j][2], C[mt][j][3]);
            }
        }

        if (kt < 15) {
            char* kb = smc + SC_KB0 + ((kt + 1) & 1) * SC_KBSTRIDE;
#pragma unroll
            for (int t = 0; t < 4; t++) {
                int f = tid + t * 512;
                int r = f >> 4, c = (f & 15) << 2;
                uint2 hp, lp;
                h2split(pre[t], hp, lp);
                *(uint2*)(kb + (r * 72 + c) * 2) = hp;
                *(uint2*)(kb + 18432 + (r * 72 + c) * 2) = lp;
            }
        }
        __syncthreads();
    }

    // combine 4 column-quad partials per row
    float* smm = (float*)(smc + SC_STATS);
    float* sml = smm + 512;
    if (tg == 0) {
#pragma unroll
        for (int mt = 0; mt < 2; mt++) {
            int rr = r1 + mt * 16;
            smm[wq * 128 + rr] = mA[mt];      sml[wq * 128 + rr] = lA[mt];
            smm[wq * 128 + rr + 8] = mB[mt];  sml[wq * 128 + rr + 8] = lB[mt];
        }
    }
    __syncthreads();
    if (tid < 128) {
        float M = smm[tid];
#pragma unroll
        for (int qd = 1; qd < 4; qd++) M = fmaxf(M, smm[qd * 128 + tid]);
        float L = 0.f;
#pragma unroll
        for (int qd = 0; qd < 4; qd++) L += sml[qd * 128 + tid] * ex2f(smm[qd * 128 + tid] - M);
        int base = hb * SEQ + qt * 128;
        g_m[base + tid] = M;
        g_l[base + tid] = L;
    }
}

// ==================== kernel 3: normalize + PV via f16-2x (A hi only) ====================
// 512 threads; double-buffered smem; warp = (wr 0..7 rows of 16, wc 0..1 col half of 32)
// buffer: AH 0 (18432), VH 18432 (9216), VL 27648 (9216) -> 36864 per buf
#define PV_PBUF 36864
#define PV_STAT 73728
#define PV_SMEM_BYTES 74752

__global__ __launch_bounds__(512, 1) void pv_mma_kernel(float* __restrict__ attn) {
    extern __shared__ char smc[];
    uint32_t sb = su32(smc);
    float* msm  = (float*)(smc + PV_STAT);
    float* ilsm = (float*)(smc + PV_STAT + 512);

    int tid = threadIdx.x, lane = tid & 31, w = tid >> 5;
    int g = lane >> 2, tg = lane & 3;
    int wr = w & 7, wc = w >> 3;
    int hb = blockIdx.x, qt = blockIdx.y;

    if (tid < 128) {
        msm[tid] = g_m[hb * SEQ + qt * 128 + tid];
        ilsm[tid] = 1.0f / g_l[hb * SEQ + qt * 128 + tid];
    }
    __syncthreads();

    float* arow = attn + (size_t)hb * SEQ * SEQ + (size_t)(qt * 128) * SEQ;
    float C[4][4];
#pragma unroll
    for (int j = 0; j < 4; j++) { C[j][0] = C[j][1] = C[j][2] = C[j][3] = 0.f; }

    float4 aR[4], vR[2];
    // prologue: load + process chunk 0 into buf 0
    {
        const float* Vp = g_Vh + ((size_t)hb * SEQ) * DHEAD;
#pragma unroll
        for (int t = 0; t < 4; t++) {
            int f = tid + t * 512;
            int r = f >> 4, c = (f & 15) << 2;
            aR[t] = *(const float4*)(arow + (size_t)r * SEQ + c);
        }
#pragma unroll
        for (int t = 0; t < 2; t++) {
            int f = tid + t * 512;
            int kk = f >> 4, dd = (f & 15) << 2;
            vR[t] = *(const float4*)(Vp + (size_t)kk * DHEAD + dd);
        }
        char* bufc = smc;
#pragma unroll
        for (int t = 0; t < 4; t++) {
            int f = tid + t * 512;
            int r = f >> 4, c = (f & 15) << 2;
            float4 v = aR[t];
            float mm = msm[r], il = ilsm[r];
            v.x = ex2f(v.x - mm) * il; v.y = ex2f(v.y - mm) * il;
            v.z = ex2f(v.z - mm) * il; v.w = ex2f(v.w - mm) * il;
            *(float4*)(arow + (size_t)r * SEQ + c) = v;
            *(uint2*)(bufc + (r * 72 + c) * 2) = h2hi(v);
        }
#pragma unroll
        for (int t = 0; t < 2; t++) {
            int f = tid + t * 512;
            int kk = f >> 4, dd = (f & 15) << 2;
            uint2 hp, lp;
            h2split(vR[t], hp, lp);
            *(uint2*)(bufc + 18432 + (kk * 72 + dd) * 2) = hp;
            *(uint2*)(bufc + 27648 + (kk * 72 + dd) * 2) = lp;
        }
    }
    __syncthreads();

    int arw = wr * 16 + (lane & 15);
    int acl = ((lane >> 4) & 1) * 8;
    int brow4 = (lane & 15);
    int bcol4 = wc * 32 + ((lane >> 4) & 1) * 8;

    for (int kc = 0; kc < 32; kc++) {
        int b = kc & 1;
        if (kc < 31) {
            const float* Vp = g_Vh + ((size_t)hb * SEQ + (kc + 1) * 64) * DHEAD;
#pragma unroll
            for (int t = 0; t < 4; t++) {
                int f = tid + t * 512;
                int r = f >> 4, c = (f & 15) << 2;
                aR[t] = *(const float4*)(arow + (size_t)r * SEQ + (kc + 1) * 64 + c);
            }
#pragma unroll
            for (int t = 0; t < 2; t++) {
                int f = tid + t * 512;
                int kk = f >> 4, dd = (f & 15) << 2;
                vR[t] = *(const float4*)(Vp + (size_t)kk * DHEAD + dd);
            }
        }
        // mma from buffer b (2-term: Ph*Vh + Ph*Vl)
        uint32_t bufb = sb + b * PV_PBUF;
        uint32_t aHf[4][4];
#pragma unroll
        for (int s = 0; s < 4; s++) {
            uint32_t off = (uint32_t)((arw * 72 + s * 16 + acl) * 2);
            ldmA(aHf[s], bufb + off);
        }
#pragma unroll
        for (int jp = 0; jp < 2; jp++) {
#pragma unroll
            for (int s = 0; s < 4; s++) {
                uint32_t boff = (uint32_t)(((s * 16 + brow4) * 72 + bcol4 + jp * 16) * 2);
                uint32_t b4H[4], b4L[4];
                ldmB4(b4H, bufb + 18432 + boff);
                ldmB4(b4L, bufb + 27648 + boff);
#pragma unroll
                for (int jj = 0; jj < 2; jj++) {
                    float* Cp = C[jp * 2 + jj];
                    mma_f16(Cp, aHf[s], b4H + jj * 2);
                    mma_f16(Cp, aHf[s], b4L + jj * 2);
                }
            }
        }
        if (kc < 31) {
            char* bufc = smc + (b ^ 1) * PV_PBUF;
#pragma unroll
            for (int t = 0; t < 4; t++) {
                int f = tid + t * 512;
                int r = f >> 4, c = (f & 15) << 2;
                float4 v = aR[t];
                float mm = msm[r], il = ilsm[r];
                v.x = ex2f(v.x - mm) * il; v.y = ex2f(v.y - mm) * il;
                v.z = ex2f(v.z - mm) * il; v.w = ex2f(v.w - mm) * il;
                *(float4*)(arow + (size_t)r * SEQ + (kc + 1) * 64 + c) = v;
                *(uint2*)(bufc + (r * 72 + c) * 2) = h2hi(v);
            }
#pragma unroll
            for (int t = 0; t < 2; t++) {
                int f = tid + t * 512;
                int kk = f >> 4, dd = (f & 15) << 2;
                uint2 hp, lp;
                h2split(vR[t], hp, lp);
                *(uint2*)(bufc + 18432 + (kk * 72 + dd) * 2) = hp;
                *(uint2*)(bufc + 27648 + (kk * 72 + dd) * 2) = lp;
            }
        }
        __syncthreads();
    }

    int h = hb >> 1, bb = hb & 1;
    int r1 = wr * 16 + g;
    float* o1 = g_oh + ((size_t)(bb * SEQ + qt * 128 + r1)) * HD + h * 64 + wc * 32 + 2 * tg;
    float* o2 = o1 + 8 * HD;
#pragma unroll
    for (int j = 0; j < 4; j++) {
        *(float2*)(o1 + j * 8) = make_float2(C[j][0], C[j][1]);
        *(float2*)(o2 + j * 8) = make_float2(C[j][2], C[j][3]);
    }
}

// ==================== kernel 4: out projection via f16-2x (A hi only) ====================
// 512 threads; double-buffered; warp = (wr 0..7 rows of 16, wc 0..1 col half of 64)
// buffer: AH 0 (18432), BH 18432 (17408), BL 35840 (17408) -> 53248 per buf
#define OP_PBUF 53248
#define OP_SMEM_BYTES 106496

__global__ __launch_bounds__(512, 1) void oproj_mma_kernel(
    const float* __restrict__ Wo, const float* __restrict__ bo, float* __restrict__ out) {
    extern __shared__ char smc[];
    uint32_t sb = su32(smc);

    int tid = threadIdx.x, lane = tid & 31, w = tid >> 5;
    int g = lane >> 2, tg = lane & 3;
    int wr = w & 7, wc = w >> 3;
    int rt = blockIdx.x, ct = blockIdx.y;

    float C[8][4];
#pragma unroll
    for (int j = 0; j < 8; j++) { C[j][0] = C[j][1] = C[j][2] = C[j][3] = 0.f; }

    float4 aR[4], bR[4];
    // prologue
    {
#pragma unroll
        for (int t = 0; t < 4; t++) {
            int f = tid + t * 512;
            int r = f >> 4, c = (f & 15) << 2;
            aR[t] = *(const float4*)(g_oh + (size_t)(rt * 128 + r) * HD + c);
        }
#pragma unroll
        for (int t = 0; t < 4; t++) {
            int f = tid + t * 512;
            int kk = f >> 5, nn = (f & 31) << 2;
            bR[t] = *(const float4*)(Wo + (size_t)kk * DO + ct * 128 + nn);
        }
        char* bufc = smc;
#pragma unroll
        for (int t = 0; t < 4; t++) {
            int f = tid + t * 512;
            int r = f >> 4, c = (f & 15) << 2;
            *(uint2*)(bufc + (r * 72 + c) * 2) = h2hi(aR[t]);
        }
#pragma unroll
        for (int t = 0; t < 4; t++) {
            int f = tid + t * 512;
            int kk = f >> 5, nn = (f & 31) << 2;
            uint2 hp, lp;
            h2split(bR[t], hp, lp);
            *(uint2*)(bufc + 18432 + (kk * 136 + nn) * 2) = hp;
            *(uint2*)(bufc + 35840 + (kk * 136 + nn) * 2) = lp;
        }
    }
    __syncthreads();

    int arw = wr * 16 + (lane & 15);
    int acl = ((lane >> 4) & 1) * 8;
    int brow4 = (lane & 15);
    int bcol4 = wc * 64 + ((lane >> 4) & 1) * 8;

    for (int kc = 0; kc < 16; kc++) {
        int b = kc & 1;
        if (kc < 15) {
#pragma unroll
            for (int t = 0; t < 4; t++) {
                int f = tid + t * 512;
                int r = f >> 4, c = (f & 15) << 2;
                aR[t] = *(const float4*)(g_oh + (size_t)(rt * 128 + r) * HD + (kc + 1) * 64 + c);
            }
#pragma unroll
            for (int t = 0; t < 4; t++) {
                int f = tid + t * 512;
                int kk = f >> 5, nn = (f & 31) << 2;
                bR[t] = *(const float4*)(Wo + (size_t)((kc + 1) * 64 + kk) * DO + ct * 128 + nn);
            }
        }
        uint32_t bufb = sb + b * OP_PBUF;
        uint32_t aHf[4][4];
#pragma unroll
        for (int s = 0; s < 4; s++) {
            uint32_t off = (uint32_t)((arw * 72 + s * 16 + acl) * 2);
            ldmA(aHf[s], bufb + off);
        }
#pragma unroll
        for (int jp = 0; jp < 4; jp++) {
#pragma unroll
            for (int s = 0; s < 4; s++) {
                uint32_t boff = (uint32_t)(((s * 16 + brow4) * 136 + bcol4 + jp * 16) * 2);
                uint32_t b4H[4], b4L[4];
                ldmB4(b4H, bufb + 18432 + boff);
                ldmB4(b4L, bufb + 35840 + boff);
#pragma unroll
                for (int jj = 0; jj < 2; jj++) {
                    float* Cp = C[jp * 2 + jj];
                    mma_f16(Cp, aHf[s], b4H + jj * 2);
                    mma_f16(Cp, aHf[s], b4L + jj * 2);
                }
            }
        }
        if (kc < 15) {
            char* bufc = smc + (b ^ 1) * OP_PBUF;
#pragma unroll
            for (int t = 0; t < 4; t++) {
                int f = tid + t * 512;
                int r = f >> 4, c = (f & 15) << 2;
                *(uint2*)(bufc + (r * 72 + c) * 2) = h2hi(aR[t]);
            }
#pragma unroll
            for (int t = 0; t < 4; t++) {
                int f = tid + t * 512;
                int kk = f >> 5, nn = (f & 31) << 2;
                uint2 hp, lp;
                h2split(bR[t], hp, lp);
                *(uint2*)(bufc + 18432 + (kk * 136 + nn) * 2) = hp;
                *(uint2*)(bufc + 35840 + (kk * 136 + nn) * 2) = lp;
            }
        }
        __syncthreads();
    }

    int r1 = wr * 16 + g;
    const float* bp = bo + ct * 128 + wc * 64;
    float* o1 = out + (size_t)(rt * 128 + r1) * DO + ct * 128 + wc * 64 + 2 * tg;
    float* o2 = o1 + 8 * DO;
#pragma unroll
    for (int j = 0; j < 8; j++) {
        int cc = j * 8 + 2 * tg;
        *(float2*)(o1 + j * 8) = make_float2(C[j][0] + bp[cc], C[j][1] + bp[cc + 1]);
        *(float2*)(o2 + j * 8) = make_float2(C[j][2] + bp[cc], C[j][3] + bp[cc + 1]);
    }
}

// ==================== launch ====================
extern "C" void kernel_launch(void* const* d_in, const int* in_sizes, int n_in,
                              void* d_out, int out_size) {
    const float* q  = (const float*)d_in[0];
    const float* k  = (const float*)d_in[1];
    const float* v  = (const float*)d_in[2];
    const float* Wq = (const float*)d_in[3];
    const float* bq = (const float*)d_in[4];
    const float* Wk = (const float*)d_in[5];
    const float* bk = (const float*)d_in[6];
    const float* Wv = (const float*)d_in[7];
    const float* bv = (const float*)d_in[8];
    const float* Wo = (const float*)d_in[9];
    const float* bo = (const float*)d_in[10];
    (void)in_sizes; (void)n_in;

    long long osz = (long long)out_size;
    float* attn = nullptr;
    float* out  = nullptr;
    if (osz >= ATTN_ELEMS + OUT_ELEMS) {
        attn = (float*)d_out;
        out  = (float*)d_out + ATTN_ELEMS;
    } else if (osz >= ATTN_ELEMS) {
        attn = (float*)d_out;
    } else {
        out = (float*)d_out;
    }
    if (!attn) cudaGetSymbolAddress((void**)&attn, g_attn_fb);

    float *Qh, *Kh, *Vh;
    cudaGetSymbolAddress((void**)&Qh, g_Qh);
    cudaGetSymbolAddress((void**)&Kh, g_Kh);
    cudaGetSymbolAddress((void**)&Vh, g_Vh);

    cudaFuncSetAttribute(scores_mma_kernel, cudaFuncAttributeMaxDynamicSharedMemorySize, SC_SMEM_BYTES);
    cudaFuncSetAttribute(pv_mma_kernel, cudaFuncAttributeMaxDynamicSharedMemorySize, PV_SMEM_BYTES);
    cudaFuncSetAttribute(oproj_mma_kernel, cudaFuncAttributeMaxDynamicSharedMemorySize, OP_SMEM_BYTES);

    proj_fused_kernel<<<dim3(64, 16, 3), 256>>>(q, k, v, Wq, bq, Wk, bk, Wv, bv, Qh, Kh, Vh);
    scores_mma_kernel<<<dim3(HB, 16), 512, SC_SMEM_BYTES>>>(attn);
    pv_mma_kernel<<<dim3(HB, 16), 512, PV_SMEM_BYTES>>>(attn);
    if (out) oproj_mma_kernel<<<dim3(32, 8), 512, OP_SMEM_BYTES>>>(Wo, bo, out);
}